// round 15
// baseline (speedup 1.0000x reference)
#include <cuda_runtime.h>
#include <cstdint>

#define BB 64
#define HH 1024
#define WW 1024
#define NN 256
#define MAX_ITERS 20
#define W9 (1.0f/9.0f)
#define P15 20               // tile pitch (15-wide rows + slack)

// scratch
__device__ int2 g_end[BB * NN];      // end coords after gravity (x,y)
__device__ int  g_meta[BB * NN];     // winner | leader<<8 | has<<16

// ---------------------------------------------------------------------------
// Kernel 1: gravity_move, one warp per point, 2 warps/block.
// Interior fast path: 15x15 raw tile via 75 aligned LDG.128; argmax steps
// keep running from SMEM while |pos - tile_center|inf <= 3 (>=2 guaranteed).
// (byte-identical to round-14)
// ---------------------------------------------------------------------------
__global__ void __launch_bounds__(64) gravity_kernel(
    const float* __restrict__ depth, const int* __restrict__ points)
{
    const int w    = threadIdx.x >> 5;
    const int lane = threadIdx.x & 31;
    const int pidx = blockIdx.x * 2 + w;          // grid = B*N/2
    const int b    = pidx >> 8;                   // N = 256
    const float* dep = depth + (size_t)b * HH * WW;

    int2 pt = *(const int2*)(points + pidx * 2);
    int px = pt.x, py = pt.y;

    __shared__ __align__(16) float tile[2][2][15 * P15 + 4];  // [warp][buf][]
    float* Tb0 = &tile[w][0][0];
    float* Tb1 = &tile[w][1][0];

    // ---- loop-invariant per-lane constants ----
    const int v0r = lane / 5,        v0s = lane - v0r * 5;
    const int ev1 = lane + 32;
    const int v1r = ev1 / 5,         v1s = ev1 - v1r * 5;
    const int ev2 = lane + 64;
    const int v2r = ev2 / 5,         v2s = ev2 - v2r * 5;
    const bool vl2 = (ev2 < 75);                  // lane < 11
    const int vg0 = v0r * WW + v0s * 4,  vs0 = v0r * P15 + v0s * 4;
    const int vg1 = v1r * WW + v1s * 4,  vs1 = v1r * P15 + v1s * 4;
    const int vg2 = v2r * WW + v2s * 4,  vs2 = v2r * P15 + v2s * 4;

    const int r0 = lane / 9,        c0 = lane - r0 * 9;
    const int e1 = lane + 32;
    const int r1 = e1 / 9,          c1 = e1 - r1 * 9;
    const int e2 = lane + 64;
    const int r2 = e2 / 9,          c2 = e2 - r2 * 9;
    const bool l3 = (lane < 17);

    const int cA  = lane;
    const int rA  = cA / 7;
    const int dyA = rA - 3,  dxA = cA - rA * 7 - 3;
    const int cB  = lane + 32;
    const int rB  = cB / 7;
    const int dyB = rB - 3,  dxB = cB - rB * 7 - 3;
    const bool hasB = (cB < 49);
    const int sA15 = (dyA + 6) * P15 + (dxA + 6);
    const int sB15 = (dyB + 6) * P15 + (dxB + 6);

    auto evalAB = [&](const float* T, int off) -> int {
        unsigned uA, uB = 0u;
        {
            const float* p = T + sA15 + off;
            float a = 0.0f;
            #pragma unroll
            for (int i2 = 0; i2 < 3; ++i2)
                #pragma unroll
                for (int j2 = 0; j2 < 3; ++j2)
                    a = fmaf(p[i2 * P15 + j2], W9, a);
            unsigned ua = __float_as_uint(a);
            uA = ((int)ua >= 0) ? (ua | 0x80000000u) : ~ua;
        }
        if (hasB) {
            const float* q = T + sB15 + off;
            float b2 = 0.0f;
            #pragma unroll
            for (int i2 = 0; i2 < 3; ++i2)
                #pragma unroll
                for (int j2 = 0; j2 < 3; ++j2)
                    b2 = fmaf(q[i2 * P15 + j2], W9, b2);
            unsigned ub = __float_as_uint(b2);
            uB = ((int)ub >= 0) ? (ub | 0x80000000u) : ~ub;
        }
        unsigned wmax = __reduce_max_sync(0xffffffffu, max(uA, uB));
        unsigned balA = __ballot_sync(0xffffffffu, uA == wmax);
        unsigned balB = __ballot_sync(0xffffffffu, uB == wmax);
        return balA ? (__ffs(balA) - 1) : (__ffs(balB) + 31);
    };

    int it = 0, trip = 0;
    bool done = false;

    while (!done) {
        float* T = (trip & 1) ? Tb1 : Tb0;
        ++trip;
        const bool int15 = (px >= 7) & (px <= WW - 13) &
                           (py >= 7) & (py <= HH - 8);     // warp-uniform

        if (int15) {
            const int cy = py, cx = px;
            const int by = cy - 7, bx = cx - 7;
            const int bx4 = bx & ~3;
            const int sh = bx - bx4;
            const float* base = dep + by * WW + bx4;
            {
                float4 v = __ldg((const float4*)(base + vg0));
                *(float4*)(T + vs0) = v;
            }
            {
                float4 v = __ldg((const float4*)(base + vg1));
                *(float4*)(T + vs1) = v;
            }
            if (vl2) {
                float4 v = __ldg((const float4*)(base + vg2));
                *(float4*)(T + vs2) = v;
            }
            __syncwarp();

            while (true) {
                int besti = evalAB(T, sh + (py - cy) * P15 + (px - cx));
                int rr  = besti / 7;
                px += besti - rr * 7 - 3;
                py += rr - 3;
                ++it;
                if (besti == 24 || it >= MAX_ITERS) { done = true; break; }
                if (px < cx - 3 || px > cx + 3 ||
                    py < cy - 3 || py > cy + 3) break;     // need fresh tile
            }
        } else {
            const int by = py - 4, bx = px - 4;
            {
                int gy = by + r0, gx = bx + c0;
                T[r0 * P15 + c0] = (gy >= 0 && gy < HH && gx >= 0 && gx < WW)
                                       ? __ldg(dep + gy * WW + gx) : 0.0f;
            }
            {
                int gy = by + r1, gx = bx + c1;
                T[r1 * P15 + c1] = (gy >= 0 && gy < HH && gx >= 0 && gx < WW)
                                       ? __ldg(dep + gy * WW + gx) : 0.0f;
            }
            if (l3) {
                int gy = by + r2, gx = bx + c2;
                T[r2 * P15 + c2] = (gy >= 0 && gy < HH && gx >= 0 && gx < WW)
                                       ? __ldg(dep + gy * WW + gx) : 0.0f;
            }
            __syncwarp();

            unsigned uA, uB = 0u;
            {
                int yc = min(max(py + dyA, 0), HH - 1);
                int xc = min(max(px + dxA, 0), WW - 1);
                const float* p = T + (yc - by - 1) * P15 + (xc - bx - 1);
                float a = 0.0f;
                #pragma unroll
                for (int i2 = 0; i2 < 3; ++i2)
                    #pragma unroll
                    for (int j2 = 0; j2 < 3; ++j2)
                        a = fmaf(p[i2 * P15 + j2], W9, a);
                unsigned ua = __float_as_uint(a);
                uA = ((int)ua >= 0) ? (ua | 0x80000000u) : ~ua;
            }
            if (hasB) {
                int yc = min(max(py + dyB, 0), HH - 1);
                int xc = min(max(px + dxB, 0), WW - 1);
                const float* q = T + (yc - by - 1) * P15 + (xc - bx - 1);
                float b2 = 0.0f;
                #pragma unroll
                for (int i2 = 0; i2 < 3; ++i2)
                    #pragma unroll
                    for (int j2 = 0; j2 < 3; ++j2)
                        b2 = fmaf(q[i2 * P15 + j2], W9, b2);
                unsigned ub = __float_as_uint(b2);
                uB = ((int)ub >= 0) ? (ub | 0x80000000u) : ~ub;
            }

            unsigned wmax = __reduce_max_sync(0xffffffffu, max(uA, uB));
            unsigned balA = __ballot_sync(0xffffffffu, uA == wmax);
            unsigned balB = __ballot_sync(0xffffffffu, uB == wmax);
            int besti = balA ? (__ffs(balA) - 1) : (__ffs(balB) + 31);

            int rr = besti / 7;
            int ny = min(max(py + rr - 3, 0), HH - 1);
            int nx = min(max(px + besti - rr * 7 - 3, 0), WW - 1);
            bool moved = (nx != px) | (ny != py);
            px = nx; py = ny; ++it;
            if (!moved || it >= MAX_ITERS) done = true;
        }
    }

    if (lane == 0) g_end[pidx] = make_int2(px, py);
}

// ---------------------------------------------------------------------------
// Kernel 2: pairwise overlap stats. 8 blocks per batch; 8 warps x 4 points.
// Packed-key REDUX reductions, exact tie-breaks. (byte-identical to round-12)
// ---------------------------------------------------------------------------
__global__ void __launch_bounds__(256) pairwise_kernel(
    const int* __restrict__ points)
{
    const int w    = threadIdx.x >> 5;
    const int lane = threadIdx.x & 31;
    const int blkInBatch = blockIdx.x & 7;        // 8 blocks per batch
    const int b    = blockIdx.x >> 3;
    const int base = b * NN;

    __shared__ int ex[NN], ey[NN], sx[NN], sy[NN];
    const int t = threadIdx.x;
    {
        int2 e = g_end[base + t];
        ex[t] = e.x;  ey[t] = e.y;
        int2 s = *(const int2*)(points + (base + t) * 2);
        sx[t] = s.x;  sy[t] = s.y;
    }
    __syncthreads();

    #pragma unroll
    for (int k = 0; k < 4; ++k) {
        const int i   = blkInBatch * 32 + w * 4 + k;
        const int exi = ex[i], eyi = ey[i];

        int cnt = 0;
        unsigned minlead = 255u;
        unsigned key = 0xffffffffu;                // (sd<<8)|j, sd < 2^21

        #pragma unroll
        for (int m = 0; m < 8; ++m) {
            int j   = lane + 32 * m;
            int ddx = exi - ex[j], ddy = eyi - ey[j];
            int de  = ddx * ddx + ddy * ddy;
            if (de < 4) {                          // dist < 2.0 <=> sq < 4
                cnt++;
                minlead = min(minlead, (unsigned)j);   // argmax(ov) = first True
                int sdx = sx[j] - exi, sdy = sy[j] - eyi;
                unsigned sd = (unsigned)(sdx * sdx + sdy * sdy);
                key = min(key, (sd << 8) | (unsigned)j);
            }
        }
        cnt     = __reduce_add_sync(0xffffffffu, cnt);
        minlead = __reduce_min_sync(0xffffffffu, minlead);
        key     = __reduce_min_sync(0xffffffffu, key);

        if (lane == 0)
            g_meta[base + i] = (int)(key & 255u) | ((int)minlead << 8) | ((cnt > 1) << 16);
    }
}

// ---------------------------------------------------------------------------
// Kernel 3: finalize coordinates + peak (exact row-major 3x3 fma chain).
// (byte-identical to round-12)
// ---------------------------------------------------------------------------
__global__ void __launch_bounds__(128) finalize_kernel(
    const float* __restrict__ depth, const int* __restrict__ points,
    float* __restrict__ out)
{
    const int gid  = blockIdx.x * 128 + threadIdx.x;   // 0..16383
    const int b    = gid >> 8;
    const int base = b * NN;
    const int i    = gid & 255;

    const int meta   = g_meta[gid];
    const int leader = (meta >> 8) & 0xff;
    const bool has   = (meta >> 16) & 1;
    const int wol    = g_meta[base + leader] & 0xff;   // winner[leader]

    int fx, fy;
    if (has) {
        if (i == wol) {
            int2 e = g_end[base + leader];
            fx = e.x; fy = e.y;
        } else {
            int2 s = *(const int2*)(points + gid * 2);
            fx = s.x; fy = s.y;
        }
    } else {
        int2 e = g_end[gid];
        fx = e.x; fy = e.y;
    }

    const float* dep = depth + (size_t)b * HH * WW;
    float acc = 0.0f;
    #pragma unroll
    for (int u = -1; u <= 1; ++u)
        #pragma unroll
        for (int v = -1; v <= 1; ++v) {
            int gy = fy + u, gx = fx + v;
            float val = (gy >= 0 && gy < HH && gx >= 0 && gx < WW)
                            ? __ldg(dep + gy * WW + gx) : 0.0f;
            acc = fmaf(val, W9, acc);
        }

    out[gid * 2 + 0] = (float)fx;
    out[gid * 2 + 1] = (float)fy;
    out[BB * NN * 2 + gid] = acc;
}

// ---------------------------------------------------------------------------
extern "C" void kernel_launch(void* const* d_in, const int* in_sizes, int n_in,
                              void* d_out, int out_size)
{
    const float* depth  = (const float*)d_in[0];   // (64,1,1024,1024) f32
    const int*   points = (const int*)d_in[1];     // (64,256,2) i32
    float* out = (float*)d_out;                    // end (B,N,2) ++ peak (B,N)

    gravity_kernel <<<(BB * NN) / 2, 64>>>(depth, points);
    pairwise_kernel<<<BB * 8,        256>>>(points);
    finalize_kernel<<<(BB * NN) / 128, 128>>>(depth, points, out);
}

// round 16
// speedup vs baseline: 1.0061x; 1.0061x over previous
#include <cuda_runtime.h>
#include <cstdint>

#define BB 64
#define HH 1024
#define WW 1024
#define NN 256
#define MAX_ITERS 20
#define W9 (1.0f/9.0f)
#define P15 20               // tile pitch (15-wide rows + slack)

// scratch
__device__ int2 g_end[BB * NN];      // end coords after gravity (x,y)
__device__ int  g_meta[BB * NN];     // winner | leader<<8 | has<<16

// ---------------------------------------------------------------------------
// Kernel 1: gravity_move, one warp per point, 2 warps/block.
// 15x15 raw tile via 75 aligned LDG.128, MOMENTUM-CENTERED at pos+last_move:
// drifting points pass through the tile center -> 2-3 steps per global trip.
// Argmax steps run from SMEM while |pos - center|inf <= 3.
// ---------------------------------------------------------------------------
__global__ void __launch_bounds__(64) gravity_kernel(
    const float* __restrict__ depth, const int* __restrict__ points)
{
    const int w    = threadIdx.x >> 5;
    const int lane = threadIdx.x & 31;
    const int pidx = blockIdx.x * 2 + w;          // grid = B*N/2
    const int b    = pidx >> 8;                   // N = 256
    const float* dep = depth + (size_t)b * HH * WW;

    int2 pt = *(const int2*)(points + pidx * 2);
    int px = pt.x, py = pt.y;

    __shared__ __align__(16) float tile[2][2][15 * P15 + 4];  // [warp][buf][]
    float* Tb0 = &tile[w][0][0];
    float* Tb1 = &tile[w][1][0];

    // ---- loop-invariant per-lane constants ----
    const int v0r = lane / 5,        v0s = lane - v0r * 5;
    const int ev1 = lane + 32;
    const int v1r = ev1 / 5,         v1s = ev1 - v1r * 5;
    const int ev2 = lane + 64;
    const int v2r = ev2 / 5,         v2s = ev2 - v2r * 5;
    const bool vl2 = (ev2 < 75);                  // lane < 11
    const int vg0 = v0r * WW + v0s * 4,  vs0 = v0r * P15 + v0s * 4;
    const int vg1 = v1r * WW + v1s * 4,  vs1 = v1r * P15 + v1s * 4;
    const int vg2 = v2r * WW + v2s * 4,  vs2 = v2r * P15 + v2s * 4;

    const int r0 = lane / 9,        c0 = lane - r0 * 9;
    const int e1 = lane + 32;
    const int r1 = e1 / 9,          c1 = e1 - r1 * 9;
    const int e2 = lane + 64;
    const int r2 = e2 / 9,          c2 = e2 - r2 * 9;
    const bool l3 = (lane < 17);

    const int cA  = lane;
    const int rA  = cA / 7;
    const int dyA = rA - 3,  dxA = cA - rA * 7 - 3;
    const int cB  = lane + 32;
    const int rB  = cB / 7;
    const int dyB = rB - 3,  dxB = cB - rB * 7 - 3;
    const bool hasB = (cB < 49);
    const int sA15 = (dyA + 6) * P15 + (dxA + 6);
    const int sB15 = (dyB + 6) * P15 + (dxB + 6);

    // unclipped candidate eval + warp argmax (exact first-index tie-break)
    auto evalAB = [&](const float* T, int off) -> int {
        unsigned uA, uB = 0u;
        {
            const float* p = T + sA15 + off;
            float a = 0.0f;
            #pragma unroll
            for (int i2 = 0; i2 < 3; ++i2)
                #pragma unroll
                for (int j2 = 0; j2 < 3; ++j2)
                    a = fmaf(p[i2 * P15 + j2], W9, a);
            unsigned ua = __float_as_uint(a);
            uA = ((int)ua >= 0) ? (ua | 0x80000000u) : ~ua;
        }
        if (hasB) {
            const float* q = T + sB15 + off;
            float b2 = 0.0f;
            #pragma unroll
            for (int i2 = 0; i2 < 3; ++i2)
                #pragma unroll
                for (int j2 = 0; j2 < 3; ++j2)
                    b2 = fmaf(q[i2 * P15 + j2], W9, b2);
            unsigned ub = __float_as_uint(b2);
            uB = ((int)ub >= 0) ? (ub | 0x80000000u) : ~ub;
        }
        unsigned wmax = __reduce_max_sync(0xffffffffu, max(uA, uB));
        unsigned balA = __ballot_sync(0xffffffffu, uA == wmax);
        unsigned balB = __ballot_sync(0xffffffffu, uB == wmax);
        return balA ? (__ffs(balA) - 1) : (__ffs(balB) + 31);
    };

    int it = 0, trip = 0;
    int ldx = 0, ldy = 0;                          // last move (momentum)
    bool done = false;

    while (!done) {
        float* T = (trip & 1) ? Tb1 : Tb0;
        ++trip;

        // momentum-centered tile, clamped into the legal interior box
        const int cx = min(max(px + ldx, 7), WW - 13);
        const int cy = min(max(py + ldy, 7), HH - 8);
        // interior iff pos within +-3 of the (legal) center; since
        // |ldx|,|ldy| <= 3 this matches the old px/py interior test exactly
        const bool int15 = (px >= cx - 3) & (px <= cx + 3) &
                           (py >= cy - 3) & (py <= cy + 3);  // warp-uniform

        if (int15) {
            const int by = cy - 7, bx = cx - 7;
            const int bx4 = bx & ~3;
            const int sh = bx - bx4;
            const float* base = dep + by * WW + bx4;
            {
                float4 v = __ldg((const float4*)(base + vg0));
                *(float4*)(T + vs0) = v;
            }
            {
                float4 v = __ldg((const float4*)(base + vg1));
                *(float4*)(T + vs1) = v;
            }
            if (vl2) {
                float4 v = __ldg((const float4*)(base + vg2));
                *(float4*)(T + vs2) = v;
            }
            __syncwarp();

            // step while the eval window stays inside the tile
            while (true) {
                int besti = evalAB(T, sh + (py - cy) * P15 + (px - cx));
                int rr  = besti / 7;
                ldx = besti - rr * 7 - 3;
                ldy = rr - 3;
                px += ldx;
                py += ldy;
                ++it;
                if (besti == 24 || it >= MAX_ITERS) { done = true; break; }
                if (px < cx - 3 || px > cx + 3 ||
                    py < cy - 3 || py > cy + 3) break;     // need fresh tile
            }
        } else {
            // ---- border: guarded 9x9 load (pitch P15), clipped candidates ----
            const int by = py - 4, bx = px - 4;
            {
                int gy = by + r0, gx = bx + c0;
                T[r0 * P15 + c0] = (gy >= 0 && gy < HH && gx >= 0 && gx < WW)
                                       ? __ldg(dep + gy * WW + gx) : 0.0f;
            }
            {
                int gy = by + r1, gx = bx + c1;
                T[r1 * P15 + c1] = (gy >= 0 && gy < HH && gx >= 0 && gx < WW)
                                       ? __ldg(dep + gy * WW + gx) : 0.0f;
            }
            if (l3) {
                int gy = by + r2, gx = bx + c2;
                T[r2 * P15 + c2] = (gy >= 0 && gy < HH && gx >= 0 && gx < WW)
                                       ? __ldg(dep + gy * WW + gx) : 0.0f;
            }
            __syncwarp();

            unsigned uA, uB = 0u;
            {
                int yc = min(max(py + dyA, 0), HH - 1);
                int xc = min(max(px + dxA, 0), WW - 1);
                const float* p = T + (yc - by - 1) * P15 + (xc - bx - 1);
                float a = 0.0f;
                #pragma unroll
                for (int i2 = 0; i2 < 3; ++i2)
                    #pragma unroll
                    for (int j2 = 0; j2 < 3; ++j2)
                        a = fmaf(p[i2 * P15 + j2], W9, a);
                unsigned ua = __float_as_uint(a);
                uA = ((int)ua >= 0) ? (ua | 0x80000000u) : ~ua;
            }
            if (hasB) {
                int yc = min(max(py + dyB, 0), HH - 1);
                int xc = min(max(px + dxB, 0), WW - 1);
                const float* q = T + (yc - by - 1) * P15 + (xc - bx - 1);
                float b2 = 0.0f;
                #pragma unroll
                for (int i2 = 0; i2 < 3; ++i2)
                    #pragma unroll
                    for (int j2 = 0; j2 < 3; ++j2)
                        b2 = fmaf(q[i2 * P15 + j2], W9, b2);
                unsigned ub = __float_as_uint(b2);
                uB = ((int)ub >= 0) ? (ub | 0x80000000u) : ~ub;
            }

            unsigned wmax = __reduce_max_sync(0xffffffffu, max(uA, uB));
            unsigned balA = __ballot_sync(0xffffffffu, uA == wmax);
            unsigned balB = __ballot_sync(0xffffffffu, uB == wmax);
            int besti = balA ? (__ffs(balA) - 1) : (__ffs(balB) + 31);

            int rr = besti / 7;
            int ny = min(max(py + rr - 3, 0), HH - 1);
            int nx = min(max(px + besti - rr * 7 - 3, 0), WW - 1);
            ldx = nx - px;  ldy = ny - py;
            bool moved = (nx != px) | (ny != py);
            px = nx; py = ny; ++it;
            if (!moved || it >= MAX_ITERS) done = true;
        }
    }

    if (lane == 0) g_end[pidx] = make_int2(px, py);
}

// ---------------------------------------------------------------------------
// Kernel 2: pairwise overlap stats. 8 blocks per batch; 8 warps x 4 points.
// Packed-key REDUX reductions, exact tie-breaks. (byte-identical to round-12)
// ---------------------------------------------------------------------------
__global__ void __launch_bounds__(256) pairwise_kernel(
    const int* __restrict__ points)
{
    const int w    = threadIdx.x >> 5;
    const int lane = threadIdx.x & 31;
    const int blkInBatch = blockIdx.x & 7;        // 8 blocks per batch
    const int b    = blockIdx.x >> 3;
    const int base = b * NN;

    __shared__ int ex[NN], ey[NN], sx[NN], sy[NN];
    const int t = threadIdx.x;
    {
        int2 e = g_end[base + t];
        ex[t] = e.x;  ey[t] = e.y;
        int2 s = *(const int2*)(points + (base + t) * 2);
        sx[t] = s.x;  sy[t] = s.y;
    }
    __syncthreads();

    #pragma unroll
    for (int k = 0; k < 4; ++k) {
        const int i   = blkInBatch * 32 + w * 4 + k;
        const int exi = ex[i], eyi = ey[i];

        int cnt = 0;
        unsigned minlead = 255u;
        unsigned key = 0xffffffffu;                // (sd<<8)|j, sd < 2^21

        #pragma unroll
        for (int m = 0; m < 8; ++m) {
            int j   = lane + 32 * m;
            int ddx = exi - ex[j], ddy = eyi - ey[j];
            int de  = ddx * ddx + ddy * ddy;
            if (de < 4) {                          // dist < 2.0 <=> sq < 4
                cnt++;
                minlead = min(minlead, (unsigned)j);   // argmax(ov) = first True
                int sdx = sx[j] - exi, sdy = sy[j] - eyi;
                unsigned sd = (unsigned)(sdx * sdx + sdy * sdy);
                key = min(key, (sd << 8) | (unsigned)j);
            }
        }
        cnt     = __reduce_add_sync(0xffffffffu, cnt);
        minlead = __reduce_min_sync(0xffffffffu, minlead);
        key     = __reduce_min_sync(0xffffffffu, key);

        if (lane == 0)
            g_meta[base + i] = (int)(key & 255u) | ((int)minlead << 8) | ((cnt > 1) << 16);
    }
}

// ---------------------------------------------------------------------------
// Kernel 3: finalize coordinates + peak (exact row-major 3x3 fma chain).
// (byte-identical to round-12)
// ---------------------------------------------------------------------------
__global__ void __launch_bounds__(128) finalize_kernel(
    const float* __restrict__ depth, const int* __restrict__ points,
    float* __restrict__ out)
{
    const int gid  = blockIdx.x * 128 + threadIdx.x;   // 0..16383
    const int b    = gid >> 8;
    const int base = b * NN;
    const int i    = gid & 255;

    const int meta   = g_meta[gid];
    const int leader = (meta >> 8) & 0xff;
    const bool has   = (meta >> 16) & 1;
    const int wol    = g_meta[base + leader] & 0xff;   // winner[leader]

    int fx, fy;
    if (has) {
        if (i == wol) {
            int2 e = g_end[base + leader];
            fx = e.x; fy = e.y;
        } else {
            int2 s = *(const int2*)(points + gid * 2);
            fx = s.x; fy = s.y;
        }
    } else {
        int2 e = g_end[gid];
        fx = e.x; fy = e.y;
    }

    const float* dep = depth + (size_t)b * HH * WW;
    float acc = 0.0f;
    #pragma unroll
    for (int u = -1; u <= 1; ++u)
        #pragma unroll
        for (int v = -1; v <= 1; ++v) {
            int gy = fy + u, gx = fx + v;
            float val = (gy >= 0 && gy < HH && gx >= 0 && gx < WW)
                            ? __ldg(dep + gy * WW + gx) : 0.0f;
            acc = fmaf(val, W9, acc);
        }

    out[gid * 2 + 0] = (float)fx;
    out[gid * 2 + 1] = (float)fy;
    out[BB * NN * 2 + gid] = acc;
}

// ---------------------------------------------------------------------------
extern "C" void kernel_launch(void* const* d_in, const int* in_sizes, int n_in,
                              void* d_out, int out_size)
{
    const float* depth  = (const float*)d_in[0];   // (64,1,1024,1024) f32
    const int*   points = (const int*)d_in[1];     // (64,256,2) i32
    float* out = (float*)d_out;                    // end (B,N,2) ++ peak (B,N)

    gravity_kernel <<<(BB * NN) / 2, 64>>>(depth, points);
    pairwise_kernel<<<BB * 8,        256>>>(points);
    finalize_kernel<<<(BB * NN) / 128, 128>>>(depth, points, out);
}